// round 1
// baseline (speedup 1.0000x reference)
#include <cuda_runtime.h>

#define SEQ_LEN   8192
#define HIDDEN    1024
#define NUM_SPANS 4096
#define MAX_W     32
#define H4        (HIDDEN / 4)   // 256 float4 per row

// Scratch for per-position attention logits (no cudaMalloc allowed).
__device__ float g_scores[SEQ_LEN];

// Kernel A: g_scores[row] = dot(emb[row], attn_w) + attn_b
// One warp per row; fully coalesced float4 loads; warp shuffle reduction.
__global__ void score_kernel(const float* __restrict__ emb,
                             const float* __restrict__ attn_w,
                             const float* __restrict__ attn_b) {
    int warp = (blockIdx.x * blockDim.x + threadIdx.x) >> 5;
    int lane = threadIdx.x & 31;
    if (warp >= SEQ_LEN) return;

    const float4* row = (const float4*)(emb) + (size_t)warp * H4;
    const float4* wv  = (const float4*)(attn_w);

    float acc = 0.0f;
#pragma unroll
    for (int j = 0; j < H4 / 32; j++) {           // 8 iterations
        float4 a = row[j * 32 + lane];
        float4 c = wv [j * 32 + lane];
        acc += a.x * c.x + a.y * c.y + a.z * c.z + a.w * c.w;
    }
#pragma unroll
    for (int off = 16; off; off >>= 1)
        acc += __shfl_xor_sync(0xffffffffu, acc, off);

    if (lane == 0) g_scores[warp] = acc + attn_b[0];
}

// Kernel B: one block (256 threads) per span.
//   warp 0: masked softmax over <=32 precomputed scores -> shared weights
//   all threads: weighted gather-sum over the span rows (float4 lanes),
//   with the i==0 / i==W row loads reused for the start/end copies.
__global__ __launch_bounds__(256) void span_kernel(
        const float* __restrict__ emb,
        const int*   __restrict__ starts,
        const int*   __restrict__ ends,
        float*       __restrict__ out) {
    __shared__ float sw[MAX_W];
    __shared__ int   s_start, s_width;

    const int span = blockIdx.x;
    const int tid  = threadIdx.x;

    if (tid < 32) {
        int s = starts[span];
        int e = ends[span];
        int W = e - s;                       // width-1, in [0, 31]
        float sc = (tid <= W) ? g_scores[s + tid] : -1e9f;

        float m = sc;
#pragma unroll
        for (int off = 16; off; off >>= 1)
            m = fmaxf(m, __shfl_xor_sync(0xffffffffu, m, off));
        float p = __expf(sc - m);            // masked lanes underflow to 0
        float sum = p;
#pragma unroll
        for (int off = 16; off; off >>= 1)
            sum += __shfl_xor_sync(0xffffffffu, sum, off);

        sw[tid] = p / sum;
        if (tid == 0) { s_start = s; s_width = W; }
    }
    __syncthreads();

    const int s = s_start;
    const int W = s_width;

    const float4* base = (const float4*)(emb) + (size_t)s * H4 + tid;
    float4*       o    = (float4*)(out) + (size_t)span * (3 * H4);

    float4 acc = make_float4(0.f, 0.f, 0.f, 0.f);

#pragma unroll 4
    for (int i = 0; i <= W; i++) {
        float4 v = base[(size_t)i * H4];     // coalesced 4 KB row read (L2 hit)
        float wi = sw[i];
        acc.x = fmaf(wi, v.x, acc.x);
        acc.y = fmaf(wi, v.y, acc.y);
        acc.z = fmaf(wi, v.z, acc.z);
        acc.w = fmaf(wi, v.w, acc.w);
        if (i == 0) o[tid]       = v;        // start_emb (reuse load)
        if (i == W) o[H4 + tid]  = v;        // end_emb   (reuse load)
    }
    o[2 * H4 + tid] = acc;                   // attn_out
}

extern "C" void kernel_launch(void* const* d_in, const int* in_sizes, int n_in,
                              void* d_out, int out_size) {
    const float* emb    = (const float*)d_in[0];
    const int*   starts = (const int*)  d_in[1];
    const int*   ends   = (const int*)  d_in[2];
    const float* attn_w = (const float*)d_in[3];
    const float* attn_b = (const float*)d_in[4];
    float*       out    = (float*)d_out;

    // 8192 rows, one warp each, 8 warps/block -> 1024 blocks
    score_kernel<<<SEQ_LEN / 8, 256>>>(emb, attn_w, attn_b);
    // one 256-thread block per span
    span_kernel<<<NUM_SPANS, 256>>>(emb, starts, ends, out);
}